// round 15
// baseline (speedup 1.0000x reference)
#include <cuda_runtime.h>
#include <cuda_fp16.h>
#include <cstdint>

#define NPIX   6400
#define NBATCH 16
#define NCLS   8
#define OUTP   160
#define INP    80

// ---------------- scratch (no dynamic allocation allowed) ----------------
__device__ __half g_XA[(size_t)NBATCH * NPIX * 256];  // Ft, later Y2  [b][n][K]
__device__ __half g_XB[(size_t)NBATCH * NPIX * 512];  // Y1
__device__ __half g_w1[512 * 256];
__device__ __half g_w2[256 * 512];
__device__ __half g_w3[128 * 256];
__device__ float g_A[NBATCH * NCLS * NPIX];
__device__ float g_cnt[NBATCH * NCLS];
__device__ float g_part[NBATCH * 50 * NCLS * 128];
__device__ int   g_ctr[NBATCH];

// ---------------- PTX helpers ----------------
__device__ __forceinline__ uint32_t smem_u32(const void* p) {
    uint32_t a;
    asm("{ .reg .u64 t; cvta.to.shared.u64 t, %1; cvt.u32.u64 %0, t; }" : "=r"(a) : "l"(p));
    return a;
}
__device__ __forceinline__ void cp16(uint32_t dst, const void* src) {
    asm volatile("cp.async.cg.shared.global [%0], [%1], 16;" :: "r"(dst), "l"(src));
}
__device__ __forceinline__ void cp_commit() {
    asm volatile("cp.async.commit_group;" ::: "memory");
}
__device__ __forceinline__ void ldm_x4(uint32_t* r, uint32_t addr) {
    asm volatile("ldmatrix.sync.aligned.m8n8.x4.shared.b16 {%0,%1,%2,%3}, [%4];"
                 : "=r"(r[0]), "=r"(r[1]), "=r"(r[2]), "=r"(r[3]) : "r"(addr));
}
__device__ __forceinline__ void ldm_x4_t(uint32_t* r, uint32_t addr) {
    asm volatile("ldmatrix.sync.aligned.m8n8.x4.trans.shared.b16 {%0,%1,%2,%3}, [%4];"
                 : "=r"(r[0]), "=r"(r[1]), "=r"(r[2]), "=r"(r[3]) : "r"(addr));
}
__device__ __forceinline__ void mma_f16(float* d, const uint32_t* a, const uint32_t* b) {
    asm volatile(
        "mma.sync.aligned.m16n8k16.row.col.f32.f16.f16.f32 "
        "{%0,%1,%2,%3}, {%4,%5,%6,%7}, {%8,%9}, {%0,%1,%2,%3};"
        : "+f"(d[0]), "+f"(d[1]), "+f"(d[2]), "+f"(d[3])
        : "r"(a[0]), "r"(a[1]), "r"(a[2]), "r"(a[3]), "r"(b[0]), "r"(b[1]));
}

// smem: stage = A tile (128x128B) + B tile (128x128B) = 32KB, 3 stages
#define A_TILE_BYTES 16384
#define STAGE_BYTES  32768
#define NSTAGE       3
#define SMEM_TOTAL   (NSTAGE * STAGE_BYTES)   // 98304 (x2 CTA = 192KB/SM)
#define HROW         136
// MODE 1 overlay: Yh fp16 [128][136] (34816 B) then Ah fp16 [16][136]
#define YH_ROW       136
#define AH_OFF       34816

// ---------------------------------------------------------------------------
// fp16 tensor-core GEMM, CTA 128n x 128m, 4 warps of 64x64, 2 CTA/SM,
// rotated 3-stage cp.async pipeline (1 barrier / K-chunk).
//   MODE 0: write fp16 (stride M) via smem-staged coalesced stores.
//   MODE 1: fused masked-pooling via tensor-core mma; last CTA per batch
//           reduces partials and writes pooled + presence to Pf (=out).
// ---------------------------------------------------------------------------
template <int K, int MODE>
__global__ void __launch_bounds__(128, 2)
gemm_f16(const __half* __restrict__ X, const __half* __restrict__ W,
         const float* __restrict__ bias,
         __half* __restrict__ Oh, float* __restrict__ Pf, int M)
{
    extern __shared__ char smem[];
    const uint32_t sb = smem_u32(smem);
    const int tid = threadIdx.x, wid = tid >> 5, lane = tid & 31;
    const int nw = wid & 1;
    const int mw = wid >> 1;
    const int b = blockIdx.z;
    const int n0 = blockIdx.x * 128;
    const int mtile = blockIdx.y * 128;
    constexpr int NCH = K >> 6;

    const int slot = tid & 7;
    const int rbase = tid >> 3;
    const uint32_t swz = (uint32_t)((rbase & 7) * 16) ^ (uint32_t)(slot * 16);
    const __half* pa = X + ((size_t)b * NPIX + n0 + rbase) * K + slot * 8;
    const __half* pb = W + (size_t)(mtile + rbase) * K + slot * 8;

    auto load_chunk = [&](int c, int s) {
        const uint32_t st = sb + (uint32_t)s * STAGE_BYTES;
        const __half* sa = pa + (size_t)c * 64;
        const __half* sbp = pb + (size_t)c * 64;
#pragma unroll
        for (int j = 0; j < 8; j++)
            cp16(st + (uint32_t)(rbase + 16 * j) * 128 + swz, sa + (size_t)j * 16 * K);
#pragma unroll
        for (int j = 0; j < 8; j++)
            cp16(st + A_TILE_BYTES + (uint32_t)(rbase + 16 * j) * 128 + swz,
                 sbp + (size_t)j * 16 * K);
        cp_commit();
    };

    float acc[4][8][4];
#pragma unroll
    for (int i = 0; i < 4; i++)
#pragma unroll
        for (int j = 0; j < 8; j++)
#pragma unroll
            for (int q = 0; q < 4; q++) acc[i][j][q] = 0.f;

    const int l7 = lane & 7;
    const int mi = lane >> 3;
    const uint32_t lsw = (uint32_t)(l7 * 16);
    const int a_row_base = nw * 64 + (mi & 1) * 8 + l7;
    const int a_colq = (mi >> 1);
    const int b_row_base = mw * 64 + (mi >> 1) * 8 + l7;
    const int b_colq = (mi & 1);

    uint32_t af[2][4][4], bf[2][4][4];

    auto load_frags = [&](uint32_t abase, uint32_t bbase, int s, int buf) {
#pragma unroll
        for (int nt = 0; nt < 4; nt++)
            ldm_x4(af[buf][nt], abase + (uint32_t)(a_row_base + nt * 16) * 128
                                 + (((uint32_t)(s * 2 + a_colq) * 16) ^ lsw));
#pragma unroll
        for (int u = 0; u < 4; u++)
            ldm_x4(bf[buf][u], bbase + (uint32_t)(b_row_base + u * 16) * 128
                                 + (((uint32_t)(s * 2 + b_colq) * 16) ^ lsw));
    };

    auto mma_group = [&](int buf) {
#pragma unroll
        for (int nt = 0; nt < 4; nt++)
#pragma unroll
            for (int u = 0; u < 4; u++) {
                mma_f16(acc[nt][u * 2 + 0], af[buf][nt], bf[buf][u] + 0);
                mma_f16(acc[nt][u * 2 + 1], af[buf][nt], bf[buf][u] + 2);
            }
    };

    load_chunk(0, 0);
    load_chunk(1, 1);
    asm volatile("cp.async.wait_group 1;" ::: "memory");
    __syncthreads();
    load_frags(sb, sb + A_TILE_BYTES, 0, 0);

#pragma unroll
    for (int c = 0; c < NCH; c++) {
        if (c + 2 < NCH) load_chunk(c + 2, (c + 2) % NSTAGE);
        else             cp_commit();

        const uint32_t abase = sb + (uint32_t)(c % NSTAGE) * STAGE_BYTES;
        const uint32_t bbase = abase + A_TILE_BYTES;

#pragma unroll
        for (int s = 0; s < 3; s++) {
            load_frags(abase, bbase, s + 1, (s + 1) & 1);
            mma_group(s & 1);
        }
        if (c + 1 < NCH) {
            asm volatile("cp.async.wait_group 1;" ::: "memory");
            __syncthreads();
            const uint32_t na = sb + (uint32_t)((c + 1) % NSTAGE) * STAGE_BYTES;
            load_frags(na, na + A_TILE_BYTES, 0, 0);
        }
        mma_group(1);
    }

    // -------- epilogue --------
    const int g = lane >> 2, tg = lane & 3;

    if (MODE == 0) {
        __half* Hsm = (__half*)smem;
        __syncthreads();
#pragma unroll
        for (int nt = 0; nt < 4; nt++) {
            const int nloc = nw * 64 + nt * 16 + g;
#pragma unroll
            for (int u = 0; u < 4; u++)
#pragma unroll
                for (int h = 0; h < 2; h++) {
                    const int m = mw * 64 + u * 16 + h * 8 + tg * 2;
                    const float* cc = acc[nt][u * 2 + h];
                    const float b0 = bias[mtile + m], b1 = bias[mtile + m + 1];
                    __half2 p0, p1;
                    p0.x = __float2half_rn(fmaxf(cc[0] + b0, 0.f));
                    p0.y = __float2half_rn(fmaxf(cc[1] + b1, 0.f));
                    p1.x = __float2half_rn(fmaxf(cc[2] + b0, 0.f));
                    p1.y = __float2half_rn(fmaxf(cc[3] + b1, 0.f));
                    *(__half2*)(Hsm + (size_t)nloc * HROW + m) = p0;
                    *(__half2*)(Hsm + (size_t)(nloc + 8) * HROW + m) = p1;
                }
        }
        __syncthreads();
        const size_t obase = ((size_t)b * NPIX + n0) * (size_t)M + mtile;
        const int ch = (tid & 15) * 8;
        const int r0 = tid >> 4;
#pragma unroll
        for (int i = 0; i < 16; i++) {
            const int row = r0 + i * 8;
            *(uint4*)(Oh + obase + (size_t)row * M + ch) =
                *(const uint4*)(Hsm + (size_t)row * HROW + ch);
        }
    } else {
        // fused pooling via mma: P[16cls x 128ch] = Ah[16 x 128pix] * Yh[128pix x 128ch]
        __half* Yh = (__half*)smem;                    // [128 pix][136]
        __half* Ah = (__half*)(smem + AH_OFF);         // [16 cls][136]
        __shared__ int s_last;
        __syncthreads();
#pragma unroll
        for (int nt = 0; nt < 4; nt++) {
            const int nloc = nw * 64 + nt * 16 + g;
#pragma unroll
            for (int u = 0; u < 4; u++)
#pragma unroll
                for (int h = 0; h < 2; h++) {
                    const int m = mw * 64 + u * 16 + h * 8 + tg * 2;
                    const float* cc = acc[nt][u * 2 + h];
                    const float b0 = bias[m], b1 = bias[m + 1];
                    __half2 p0, p1;
                    p0.x = __float2half_rn(fmaxf(cc[0] + b0, 0.f));
                    p0.y = __float2half_rn(fmaxf(cc[1] + b1, 0.f));
                    p1.x = __float2half_rn(fmaxf(cc[2] + b0, 0.f));
                    p1.y = __float2half_rn(fmaxf(cc[3] + b1, 0.f));
                    *(__half2*)(Yh + (size_t)nloc * YH_ROW + m) = p0;
                    *(__half2*)(Yh + (size_t)(nloc + 8) * YH_ROW + m) = p1;
                }
        }
#pragma unroll
        for (int k = 0; k < 16; k++)
            Ah[k * YH_ROW + tid] = (k < NCLS)
                ? __float2half_rn(g_A[(size_t)(b * NCLS + k) * NPIX + n0 + tid])
                : __half(0.f);
        __syncthreads();

        const uint32_t yh = sb;
        const uint32_t ah = sb + AH_OFF;
        const int c0 = wid * 32;
        float pc[4][4];
#pragma unroll
        for (int t = 0; t < 4; t++)
#pragma unroll
            for (int q = 0; q < 4; q++) pc[t][q] = 0.f;

#pragma unroll
        for (int ks = 0; ks < 8; ks++) {
            uint32_t Af[4];
            ldm_x4(Af, ah + (uint32_t)((mi & 1) * 8 + l7) * (YH_ROW * 2)
                       + (uint32_t)(ks * 32 + (mi >> 1) * 16));
#pragma unroll
            for (int cg = 0; cg < 2; cg++) {
                uint32_t Bf[4];
                ldm_x4_t(Bf, yh + (uint32_t)(ks * 16 + (mi & 1) * 8 + l7) * (YH_ROW * 2)
                             + (uint32_t)(c0 + cg * 16 + (mi >> 1) * 8) * 2);
                mma_f16(pc[cg * 2 + 0], Af, Bf + 0);
                mma_f16(pc[cg * 2 + 1], Af, Bf + 2);
            }
        }
        // partials for this 128-pixel chunk
        {
            float* dst = g_part + (((size_t)b * 50 + blockIdx.x) * NCLS + g) * 128;
#pragma unroll
            for (int t = 0; t < 4; t++)
                *(float2*)(dst + c0 + t * 8 + tg * 2) = make_float2(pc[t][0], pc[t][1]);
        }

        // ---- last CTA of this batch reduces all 50 chunks (deterministic order)
        __syncthreads();
        if (tid == 0) {
            __threadfence();
            s_last = (atomicAdd(&g_ctr[b], 1) == 49) ? 1 : 0;
        }
        __syncthreads();
        if (s_last) {
            __threadfence();   // acquire side
            const float* pb2 = g_part + (size_t)b * 50 * NCLS * 128;
            const int c = tid;
#pragma unroll
            for (int k = 0; k < NCLS; k++) {
                float s = 0.f;
                for (int ch2 = 0; ch2 < 50; ch2++)
                    s += pb2[((size_t)ch2 * NCLS + k) * 128 + c];
                const float cv = g_cnt[b * NCLS + k];
                Pf[((size_t)b * NCLS + k) * 128 + c] = s / (cv + 1e-8f);
                if (c == 0) Pf[16384 + b * NCLS + k] = (cv > 0.f) ? 1.f : 0.f;
            }
        }
    }
}

// ---------------------------------------------------------------------------
// prep_all: one kernel, role dispatch by block range. 256 threads/block.
// ---------------------------------------------------------------------------
#define PB_W    512
#define PB_T    6912
#define PB_G    7312
#define PB_H    7328

__global__ void __launch_bounds__(256)
prep_all(const float* __restrict__ w1, const float* __restrict__ w2,
         const float* __restrict__ w3, const float* __restrict__ f,
         const int* __restrict__ lbl)
{
    __shared__ __half ts_h[64][72];   // transposed fp16 tile [n][c]
    const int bx = blockIdx.x, tid = threadIdx.x;

    if (bx < PB_W) {
        const int i = bx * 256 + tid;
        if (i < 512 * 256) g_w1[i] = __float2half_rn(w1[i]);
        if (i < 256 * 512) g_w2[i] = __float2half_rn(w2[i]);
        if (i < 128 * 256) g_w3[i] = __float2half_rn(w3[i]);
        return;
    }
    if (bx < PB_T) {
        const int t = bx - PB_W;
        const int nt = t % 100;
        const int rem = t / 100;
        const int ct = rem & 3;
        const int b = rem >> 2;
        const int n0 = nt * 64, c0 = ct * 64;
        // load + convert + transpose into smem: thread (q,r)
        const int q = tid & 15, r = tid >> 4;
#pragma unroll
        for (int cc = 0; cc < 64; cc += 16) {
            float4 v = *(const float4*)(f + ((size_t)b * 256 + c0 + cc + r) * NPIX
                                          + n0 + q * 4);
            ts_h[q * 4 + 0][cc + r] = __float2half_rn(v.x);
            ts_h[q * 4 + 1][cc + r] = __float2half_rn(v.y);
            ts_h[q * 4 + 2][cc + r] = __float2half_rn(v.z);
            ts_h[q * 4 + 3][cc + r] = __float2half_rn(v.w);
        }
        __syncthreads();
        // store: 16B coalesced; s = chunk within 64-ch row (8 chunks), rr = row
        const int s = tid & 7, rr = tid >> 3;   // rr: 0..31
#pragma unroll
        for (int p = 0; p < 2; p++) {
            const int nn = rr + p * 32;
            *(uint4*)(g_XA + ((size_t)b * NPIX + n0 + nn) * 256 + c0 + s * 8) =
                *(const uint4*)(&ts_h[nn][s * 8]);
        }
        return;
    }
    if (bx < PB_G) {
        const int idx = (bx - PB_T) * 256 + tid;
        const int jx = idx % INP;
        const int t = idx / INP;
        const int jy = t % INP;
        const int b = t / INP;
        const int* L = lbl + (size_t)b * OUTP * OUTP;

        int yo[4], xo[4];
        float wy[4], wx[4];
        yo[0] = 2 * jy;     wy[0] = (jy == 0) ? 1.0f : 0.75f;
        yo[1] = 2 * jy + 1; wy[1] = (jy == INP - 1) ? 1.0f : 0.75f;
        yo[2] = (jy > 0) ? 2 * jy - 1 : 0;         wy[2] = (jy > 0) ? 0.25f : 0.f;
        yo[3] = (jy < INP - 1) ? 2 * jy + 2 : 0;   wy[3] = (jy < INP - 1) ? 0.25f : 0.f;
        xo[0] = 2 * jx;     wx[0] = (jx == 0) ? 1.0f : 0.75f;
        xo[1] = 2 * jx + 1; wx[1] = (jx == INP - 1) ? 1.0f : 0.75f;
        xo[2] = (jx > 0) ? 2 * jx - 1 : 0;         wx[2] = (jx > 0) ? 0.25f : 0.f;
        xo[3] = (jx < INP - 1) ? 2 * jx + 2 : 0;   wx[3] = (jx < INP - 1) ? 0.25f : 0.f;

        float a[NCLS] = {0.f, 0.f, 0.f, 0.f, 0.f, 0.f, 0.f, 0.f};
#pragma unroll
        for (int iy = 0; iy < 4; iy++) {
            if (wy[iy] == 0.f) continue;
            const int* Lr = L + yo[iy] * OUTP;
#pragma unroll
            for (int ix = 0; ix < 4; ix++) {
                const float w = wy[iy] * wx[ix];
                if (w != 0.f) a[Lr[xo[ix]]] += w;
            }
        }
        const int cell = jy * INP + jx;
#pragma unroll
        for (int k = 0; k < NCLS; k++)
            g_A[(size_t)(b * NCLS + k) * NPIX + cell] = a[k];
        return;
    }
    {
        __shared__ int h[NCLS];
        const int b = bx - PB_G;
        if (tid < NCLS) h[tid] = 0;
        if (tid == 0) g_ctr[b] = 0;   // reset completion counter (graph-replay safe)
        __syncthreads();
        const int* L = lbl + (size_t)b * OUTP * OUTP;
        for (int i = tid; i < OUTP * OUTP; i += 256)
            atomicAdd(&h[L[i]], 1);
        __syncthreads();
        if (tid < NCLS) g_cnt[b * NCLS + tid] = (float)h[tid];
    }
}

// ---------------------------------------------------------------------------
extern "C" void kernel_launch(void* const* d_in, const int* in_sizes, int n_in,
                              void* d_out, int out_size) {
    const float* feature = (const float*)d_in[0];
    const int*   label   = (const int*)d_in[1];
    const float* w1 = (const float*)d_in[2];
    const float* b1 = (const float*)d_in[3];
    const float* w2 = (const float*)d_in[4];
    const float* b2 = (const float*)d_in[5];
    const float* w3 = (const float*)d_in[6];
    const float* b3 = (const float*)d_in[7];
    float* out = (float*)d_out;

    void *xa, *xb, *w1d, *w2d, *w3d;
    cudaGetSymbolAddress(&xa, g_XA);
    cudaGetSymbolAddress(&xb, g_XB);
    cudaGetSymbolAddress(&w1d, g_w1);
    cudaGetSymbolAddress(&w2d, g_w2);
    cudaGetSymbolAddress(&w3d, g_w3);

    cudaFuncSetAttribute(gemm_f16<256, 0>, cudaFuncAttributeMaxDynamicSharedMemorySize, SMEM_TOTAL);
    cudaFuncSetAttribute(gemm_f16<512, 0>, cudaFuncAttributeMaxDynamicSharedMemorySize, SMEM_TOTAL);
    cudaFuncSetAttribute(gemm_f16<256, 1>, cudaFuncAttributeMaxDynamicSharedMemorySize, SMEM_TOTAL);

    prep_all<<<PB_H, 256>>>(w1, w2, w3, feature, label);

    // Y1 = relu(W1 Ft + b1): [b][n][512] fp16
    gemm_f16<256, 0><<<dim3(50, 4, 16), 128, SMEM_TOTAL>>>(
        (const __half*)xa, (const __half*)w1d, b1, (__half*)xb, nullptr, 512);
    // Y2 = relu(W2 Y1 + b2): [b][n][256] fp16
    gemm_f16<512, 0><<<dim3(50, 2, 16), 128, SMEM_TOTAL>>>(
        (const __half*)xb, (const __half*)w2d, b2, (__half*)xa, nullptr, 256);
    // Y3 GEMM + mma pooling + last-CTA finalize (writes pooled & presence to out)
    gemm_f16<256, 1><<<dim3(50, 1, 16), 128, SMEM_TOTAL>>>(
        (const __half*)xa, (const __half*)w3d, b3, nullptr, out, 128);
}

// round 16
// speedup vs baseline: 1.0305x; 1.0305x over previous
#include <cuda_runtime.h>
#include <cuda_fp16.h>
#include <cstdint>

#define NPIX   6400
#define NBATCH 16
#define NCLS   8
#define OUTP   160
#define INP    80

// ---------------- scratch (no dynamic allocation allowed) ----------------
__device__ __half g_XA[(size_t)NBATCH * NPIX * 256];  // Ft, later Y2  [b][n][K]
__device__ __half g_XB[(size_t)NBATCH * NPIX * 512];  // Y1
__device__ __half g_w1[512 * 256];
__device__ __half g_w2[256 * 512];
__device__ __half g_w3[128 * 256];
__device__ float g_A[NBATCH * NCLS * NPIX];
__device__ float g_cnt[NBATCH * NCLS];
__device__ float g_part[NBATCH * 50 * NCLS * 128];

// ---------------- PTX helpers ----------------
__device__ __forceinline__ uint32_t smem_u32(const void* p) {
    uint32_t a;
    asm("{ .reg .u64 t; cvta.to.shared.u64 t, %1; cvt.u32.u64 %0, t; }" : "=r"(a) : "l"(p));
    return a;
}
__device__ __forceinline__ void cp16(uint32_t dst, const void* src) {
    asm volatile("cp.async.cg.shared.global [%0], [%1], 16;" :: "r"(dst), "l"(src));
}
__device__ __forceinline__ void cp_commit() {
    asm volatile("cp.async.commit_group;" ::: "memory");
}
__device__ __forceinline__ void ldm_x4(uint32_t* r, uint32_t addr) {
    asm volatile("ldmatrix.sync.aligned.m8n8.x4.shared.b16 {%0,%1,%2,%3}, [%4];"
                 : "=r"(r[0]), "=r"(r[1]), "=r"(r[2]), "=r"(r[3]) : "r"(addr));
}
__device__ __forceinline__ void ldm_x4_t(uint32_t* r, uint32_t addr) {
    asm volatile("ldmatrix.sync.aligned.m8n8.x4.trans.shared.b16 {%0,%1,%2,%3}, [%4];"
                 : "=r"(r[0]), "=r"(r[1]), "=r"(r[2]), "=r"(r[3]) : "r"(addr));
}
__device__ __forceinline__ void mma_f16(float* d, const uint32_t* a, const uint32_t* b) {
    asm volatile(
        "mma.sync.aligned.m16n8k16.row.col.f32.f16.f16.f32 "
        "{%0,%1,%2,%3}, {%4,%5,%6,%7}, {%8,%9}, {%0,%1,%2,%3};"
        : "+f"(d[0]), "+f"(d[1]), "+f"(d[2]), "+f"(d[3])
        : "r"(a[0]), "r"(a[1]), "r"(a[2]), "r"(a[3]), "r"(b[0]), "r"(b[1]));
}

// smem: stage = A tile (128x128B) + B tile (128x128B) = 32KB, 3 stages
#define A_TILE_BYTES 16384
#define STAGE_BYTES  32768
#define NSTAGE       3
#define SMEM_TOTAL   (NSTAGE * STAGE_BYTES)   // 98304 (x2 CTA = 192KB/SM)
#define HROW         136
// MODE 1 overlay: Yh fp16 [128][136] (34816 B) then Ah fp16 [16][136]
#define YH_ROW       136
#define AH_OFF       34816

// ---------------------------------------------------------------------------
// fp16 tensor-core GEMM, CTA 128n x 128m, 4 warps of 64x64, 2 CTA/SM,
// rotated 3-stage cp.async pipeline (1 barrier / K-chunk).
//   MODE 0: write fp16 (stride M) via smem-staged coalesced stores.
//   MODE 1: fused masked-pooling via tensor-core mma -> partials in Pf.
// ---------------------------------------------------------------------------
template <int K, int MODE>
__global__ void __launch_bounds__(128, 2)
gemm_f16(const __half* __restrict__ X, const __half* __restrict__ W,
         const float* __restrict__ bias,
         __half* __restrict__ Oh, float* __restrict__ Pf, int M)
{
    extern __shared__ char smem[];
    const uint32_t sb = smem_u32(smem);
    const int tid = threadIdx.x, wid = tid >> 5, lane = tid & 31;
    const int nw = wid & 1;
    const int mw = wid >> 1;
    const int b = blockIdx.z;
    const int n0 = blockIdx.x * 128;
    const int mtile = blockIdx.y * 128;
    constexpr int NCH = K >> 6;

    const int slot = tid & 7;
    const int rbase = tid >> 3;
    const uint32_t swz = (uint32_t)((rbase & 7) * 16) ^ (uint32_t)(slot * 16);
    const __half* pa = X + ((size_t)b * NPIX + n0 + rbase) * K + slot * 8;
    const __half* pb = W + (size_t)(mtile + rbase) * K + slot * 8;

    auto load_chunk = [&](int c, int s) {
        const uint32_t st = sb + (uint32_t)s * STAGE_BYTES;
        const __half* sa = pa + (size_t)c * 64;
        const __half* sbp = pb + (size_t)c * 64;
#pragma unroll
        for (int j = 0; j < 8; j++)
            cp16(st + (uint32_t)(rbase + 16 * j) * 128 + swz, sa + (size_t)j * 16 * K);
#pragma unroll
        for (int j = 0; j < 8; j++)
            cp16(st + A_TILE_BYTES + (uint32_t)(rbase + 16 * j) * 128 + swz,
                 sbp + (size_t)j * 16 * K);
        cp_commit();
    };

    float acc[4][8][4];
#pragma unroll
    for (int i = 0; i < 4; i++)
#pragma unroll
        for (int j = 0; j < 8; j++)
#pragma unroll
            for (int q = 0; q < 4; q++) acc[i][j][q] = 0.f;

    const int l7 = lane & 7;
    const int mi = lane >> 3;
    const uint32_t lsw = (uint32_t)(l7 * 16);
    const int a_row_base = nw * 64 + (mi & 1) * 8 + l7;
    const int a_colq = (mi >> 1);
    const int b_row_base = mw * 64 + (mi >> 1) * 8 + l7;
    const int b_colq = (mi & 1);

    uint32_t af[2][4][4], bf[2][4][4];

    auto load_frags = [&](uint32_t abase, uint32_t bbase, int s, int buf) {
#pragma unroll
        for (int nt = 0; nt < 4; nt++)
            ldm_x4(af[buf][nt], abase + (uint32_t)(a_row_base + nt * 16) * 128
                                 + (((uint32_t)(s * 2 + a_colq) * 16) ^ lsw));
#pragma unroll
        for (int u = 0; u < 4; u++)
            ldm_x4(bf[buf][u], bbase + (uint32_t)(b_row_base + u * 16) * 128
                                 + (((uint32_t)(s * 2 + b_colq) * 16) ^ lsw));
    };

    auto mma_group = [&](int buf) {
#pragma unroll
        for (int nt = 0; nt < 4; nt++)
#pragma unroll
            for (int u = 0; u < 4; u++) {
                mma_f16(acc[nt][u * 2 + 0], af[buf][nt], bf[buf][u] + 0);
                mma_f16(acc[nt][u * 2 + 1], af[buf][nt], bf[buf][u] + 2);
            }
    };

    load_chunk(0, 0);
    load_chunk(1, 1);
    asm volatile("cp.async.wait_group 1;" ::: "memory");
    __syncthreads();
    load_frags(sb, sb + A_TILE_BYTES, 0, 0);

#pragma unroll
    for (int c = 0; c < NCH; c++) {
        if (c + 2 < NCH) load_chunk(c + 2, (c + 2) % NSTAGE);
        else             cp_commit();

        const uint32_t abase = sb + (uint32_t)(c % NSTAGE) * STAGE_BYTES;
        const uint32_t bbase = abase + A_TILE_BYTES;

#pragma unroll
        for (int s = 0; s < 3; s++) {
            load_frags(abase, bbase, s + 1, (s + 1) & 1);
            mma_group(s & 1);
        }
        if (c + 1 < NCH) {
            asm volatile("cp.async.wait_group 1;" ::: "memory");
            __syncthreads();
            const uint32_t na = sb + (uint32_t)((c + 1) % NSTAGE) * STAGE_BYTES;
            load_frags(na, na + A_TILE_BYTES, 0, 0);
        }
        mma_group(1);
    }

    // -------- epilogue --------
    const int g = lane >> 2, tg = lane & 3;

    if (MODE == 0) {
        __half* Hsm = (__half*)smem;
        __syncthreads();
#pragma unroll
        for (int nt = 0; nt < 4; nt++) {
            const int nloc = nw * 64 + nt * 16 + g;
#pragma unroll
            for (int u = 0; u < 4; u++)
#pragma unroll
                for (int h = 0; h < 2; h++) {
                    const int m = mw * 64 + u * 16 + h * 8 + tg * 2;
                    const float* cc = acc[nt][u * 2 + h];
                    const float b0 = bias[mtile + m], b1 = bias[mtile + m + 1];
                    __half2 p0, p1;
                    p0.x = __float2half_rn(fmaxf(cc[0] + b0, 0.f));
                    p0.y = __float2half_rn(fmaxf(cc[1] + b1, 0.f));
                    p1.x = __float2half_rn(fmaxf(cc[2] + b0, 0.f));
                    p1.y = __float2half_rn(fmaxf(cc[3] + b1, 0.f));
                    *(__half2*)(Hsm + (size_t)nloc * HROW + m) = p0;
                    *(__half2*)(Hsm + (size_t)(nloc + 8) * HROW + m) = p1;
                }
        }
        __syncthreads();
        const size_t obase = ((size_t)b * NPIX + n0) * (size_t)M + mtile;
        const int ch = (tid & 15) * 8;
        const int r0 = tid >> 4;
#pragma unroll
        for (int i = 0; i < 16; i++) {
            const int row = r0 + i * 8;
            *(uint4*)(Oh + obase + (size_t)row * M + ch) =
                *(const uint4*)(Hsm + (size_t)row * HROW + ch);
        }
    } else {
        // fused pooling via mma: P[16cls x 128ch] = Ah[16 x 128pix] * Yh[128pix x 128ch]
        __half* Yh = (__half*)smem;                    // [128 pix][136]
        __half* Ah = (__half*)(smem + AH_OFF);         // [16 cls][136]
        __syncthreads();
#pragma unroll
        for (int nt = 0; nt < 4; nt++) {
            const int nloc = nw * 64 + nt * 16 + g;
#pragma unroll
            for (int u = 0; u < 4; u++)
#pragma unroll
                for (int h = 0; h < 2; h++) {
                    const int m = mw * 64 + u * 16 + h * 8 + tg * 2;
                    const float* cc = acc[nt][u * 2 + h];
                    const float b0 = bias[m], b1 = bias[m + 1];
                    __half2 p0, p1;
                    p0.x = __float2half_rn(fmaxf(cc[0] + b0, 0.f));
                    p0.y = __float2half_rn(fmaxf(cc[1] + b1, 0.f));
                    p1.x = __float2half_rn(fmaxf(cc[2] + b0, 0.f));
                    p1.y = __float2half_rn(fmaxf(cc[3] + b1, 0.f));
                    *(__half2*)(Yh + (size_t)nloc * YH_ROW + m) = p0;
                    *(__half2*)(Yh + (size_t)(nloc + 8) * YH_ROW + m) = p1;
                }
        }
#pragma unroll
        for (int k = 0; k < 16; k++)
            Ah[k * YH_ROW + tid] = (k < NCLS)
                ? __float2half_rn(g_A[(size_t)(b * NCLS + k) * NPIX + n0 + tid])
                : __half(0.f);
        __syncthreads();

        const uint32_t yh = sb;
        const uint32_t ah = sb + AH_OFF;
        const int c0 = wid * 32;
        float pc[4][4];
#pragma unroll
        for (int t = 0; t < 4; t++)
#pragma unroll
            for (int q = 0; q < 4; q++) pc[t][q] = 0.f;

#pragma unroll
        for (int ks = 0; ks < 8; ks++) {
            uint32_t Af[4];
            ldm_x4(Af, ah + (uint32_t)((mi & 1) * 8 + l7) * (YH_ROW * 2)
                       + (uint32_t)(ks * 32 + (mi >> 1) * 16));
#pragma unroll
            for (int cg = 0; cg < 2; cg++) {
                uint32_t Bf[4];
                ldm_x4_t(Bf, yh + (uint32_t)(ks * 16 + (mi & 1) * 8 + l7) * (YH_ROW * 2)
                             + (uint32_t)(c0 + cg * 16 + (mi >> 1) * 8) * 2);
                mma_f16(pc[cg * 2 + 0], Af, Bf + 0);
                mma_f16(pc[cg * 2 + 1], Af, Bf + 2);
            }
        }
        // pc[t]: c0,c1 = class g; c2,c3 = class g+8 (zero pad)
        if (g < NCLS) {
            float* dst = Pf + (((size_t)b * 50 + blockIdx.x) * NCLS + g) * 128;
#pragma unroll
            for (int t = 0; t < 4; t++)
                *(float2*)(dst + c0 + t * 8 + tg * 2) = make_float2(pc[t][0], pc[t][1]);
        }
    }
}

// ---------------------------------------------------------------------------
// prep_all: one kernel, role dispatch by block range. 256 threads/block.
// ---------------------------------------------------------------------------
#define PB_W    512
#define PB_T    6912
#define PB_G    7312
#define PB_H    7328

__global__ void __launch_bounds__(256)
prep_all(const float* __restrict__ w1, const float* __restrict__ w2,
         const float* __restrict__ w3, const float* __restrict__ f,
         const int* __restrict__ lbl)
{
    __shared__ __half ts_h[64][72];   // transposed fp16 tile [n][c]
    const int bx = blockIdx.x, tid = threadIdx.x;

    if (bx < PB_W) {
        const int i = bx * 256 + tid;
        if (i < 512 * 256) g_w1[i] = __float2half_rn(w1[i]);
        if (i < 256 * 512) g_w2[i] = __float2half_rn(w2[i]);
        if (i < 128 * 256) g_w3[i] = __float2half_rn(w3[i]);
        return;
    }
    if (bx < PB_T) {
        const int t = bx - PB_W;
        const int nt = t % 100;
        const int rem = t / 100;
        const int ct = rem & 3;
        const int b = rem >> 2;
        const int n0 = nt * 64, c0 = ct * 64;
        // load + convert + transpose into smem: thread (q,r)
        const int q = tid & 15, r = tid >> 4;
#pragma unroll
        for (int cc = 0; cc < 64; cc += 16) {
            float4 v = *(const float4*)(f + ((size_t)b * 256 + c0 + cc + r) * NPIX
                                          + n0 + q * 4);
            ts_h[q * 4 + 0][cc + r] = __float2half_rn(v.x);
            ts_h[q * 4 + 1][cc + r] = __float2half_rn(v.y);
            ts_h[q * 4 + 2][cc + r] = __float2half_rn(v.z);
            ts_h[q * 4 + 3][cc + r] = __float2half_rn(v.w);
        }
        __syncthreads();
        // store: 16B coalesced; s = chunk within 64-ch row (8), rr = row (0..31)
        const int s = tid & 7, rr = tid >> 3;
#pragma unroll
        for (int p = 0; p < 2; p++) {
            const int nn = rr + p * 32;
            *(uint4*)(g_XA + ((size_t)b * NPIX + n0 + nn) * 256 + c0 + s * 8) =
                *(const uint4*)(&ts_h[nn][s * 8]);
        }
        return;
    }
    if (bx < PB_G) {
        const int idx = (bx - PB_T) * 256 + tid;
        const int jx = idx % INP;
        const int t = idx / INP;
        const int jy = t % INP;
        const int b = t / INP;
        const int* L = lbl + (size_t)b * OUTP * OUTP;

        int yo[4], xo[4];
        float wy[4], wx[4];
        yo[0] = 2 * jy;     wy[0] = (jy == 0) ? 1.0f : 0.75f;
        yo[1] = 2 * jy + 1; wy[1] = (jy == INP - 1) ? 1.0f : 0.75f;
        yo[2] = (jy > 0) ? 2 * jy - 1 : 0;         wy[2] = (jy > 0) ? 0.25f : 0.f;
        yo[3] = (jy < INP - 1) ? 2 * jy + 2 : 0;   wy[3] = (jy < INP - 1) ? 0.25f : 0.f;
        xo[0] = 2 * jx;     wx[0] = (jx == 0) ? 1.0f : 0.75f;
        xo[1] = 2 * jx + 1; wx[1] = (jx == INP - 1) ? 1.0f : 0.75f;
        xo[2] = (jx > 0) ? 2 * jx - 1 : 0;         wx[2] = (jx > 0) ? 0.25f : 0.f;
        xo[3] = (jx < INP - 1) ? 2 * jx + 2 : 0;   wx[3] = (jx < INP - 1) ? 0.25f : 0.f;

        float a[NCLS] = {0.f, 0.f, 0.f, 0.f, 0.f, 0.f, 0.f, 0.f};
#pragma unroll
        for (int iy = 0; iy < 4; iy++) {
            if (wy[iy] == 0.f) continue;
            const int* Lr = L + yo[iy] * OUTP;
#pragma unroll
            for (int ix = 0; ix < 4; ix++) {
                const float w = wy[iy] * wx[ix];
                if (w != 0.f) a[Lr[xo[ix]]] += w;
            }
        }
        const int cell = jy * INP + jx;
#pragma unroll
        for (int k = 0; k < NCLS; k++)
            g_A[(size_t)(b * NCLS + k) * NPIX + cell] = a[k];
        return;
    }
    {
        __shared__ int h[NCLS];
        const int b = bx - PB_G;
        if (tid < NCLS) h[tid] = 0;
        __syncthreads();
        const int* L = lbl + (size_t)b * OUTP * OUTP;
        for (int i = tid; i < OUTP * OUTP; i += 256)
            atomicAdd(&h[L[i]], 1);
        __syncthreads();
        if (tid < NCLS) g_cnt[b * NCLS + tid] = (float)h[tid];
    }
}

// ---------------------------------------------------------------------------
__global__ void pool_final(float* __restrict__ out) {
    const int b = blockIdx.x;
    const int k = threadIdx.x >> 7, c = threadIdx.x & 127;
    float s = 0.f;
    for (int ch = 0; ch < 50; ch++)
        s += g_part[(((size_t)b * 50 + ch) * NCLS + k) * 128 + c];
    const float cv = g_cnt[b * NCLS + k];
    out[((size_t)b * NCLS + k) * 128 + c] = s / (cv + 1e-8f);
    if (c == 0) out[16384 + b * NCLS + k] = (cv > 0.f) ? 1.f : 0.f;
}

// ---------------------------------------------------------------------------
extern "C" void kernel_launch(void* const* d_in, const int* in_sizes, int n_in,
                              void* d_out, int out_size) {
    const float* feature = (const float*)d_in[0];
    const int*   label   = (const int*)d_in[1];
    const float* w1 = (const float*)d_in[2];
    const float* b1 = (const float*)d_in[3];
    const float* w2 = (const float*)d_in[4];
    const float* b2 = (const float*)d_in[5];
    const float* w3 = (const float*)d_in[6];
    const float* b3 = (const float*)d_in[7];
    float* out = (float*)d_out;

    void *xa, *xb, *w1d, *w2d, *w3d, *part;
    cudaGetSymbolAddress(&xa, g_XA);
    cudaGetSymbolAddress(&xb, g_XB);
    cudaGetSymbolAddress(&w1d, g_w1);
    cudaGetSymbolAddress(&w2d, g_w2);
    cudaGetSymbolAddress(&w3d, g_w3);
    cudaGetSymbolAddress(&part, g_part);

    cudaFuncSetAttribute(gemm_f16<256, 0>, cudaFuncAttributeMaxDynamicSharedMemorySize, SMEM_TOTAL);
    cudaFuncSetAttribute(gemm_f16<512, 0>, cudaFuncAttributeMaxDynamicSharedMemorySize, SMEM_TOTAL);
    cudaFuncSetAttribute(gemm_f16<256, 1>, cudaFuncAttributeMaxDynamicSharedMemorySize, SMEM_TOTAL);

    prep_all<<<PB_H, 256>>>(w1, w2, w3, feature, label);

    // Y1 = relu(W1 Ft + b1): [b][n][512] fp16
    gemm_f16<256, 0><<<dim3(50, 4, 16), 128, SMEM_TOTAL>>>(
        (const __half*)xa, (const __half*)w1d, b1, (__half*)xb, nullptr, 512);
    // Y2 = relu(W2 Y1 + b2): [b][n][256] fp16
    gemm_f16<512, 0><<<dim3(50, 2, 16), 128, SMEM_TOTAL>>>(
        (const __half*)xb, (const __half*)w2d, b2, (__half*)xa, nullptr, 256);
    // Y3 GEMM + mma pooling partials
    gemm_f16<256, 1><<<dim3(50, 1, 16), 128, SMEM_TOTAL>>>(
        (const __half*)xa, (const __half*)w3d, b3, nullptr, (float*)part, 128);

    pool_final<<<16, 1024>>>(out);
}

// round 17
// speedup vs baseline: 1.0987x; 1.0662x over previous
#include <cuda_runtime.h>
#include <cuda_fp16.h>
#include <cstdint>

#define NPIX   6400
#define NBATCH 16
#define NCLS   8
#define OUTP   160
#define INP    80

// ---------------- scratch (no dynamic allocation allowed) ----------------
__device__ __half g_XA[(size_t)NBATCH * NPIX * 256];  // Ft, later Y2  [b][n][K]
__device__ __half g_XB[(size_t)NBATCH * NPIX * 512];  // Y1
__device__ __half g_w1[512 * 256];
__device__ __half g_w2[256 * 512];
__device__ __half g_w3[128 * 256];
__device__ float g_A[NBATCH * NCLS * NPIX];
__device__ float g_cnt[NBATCH * NCLS];   // stores 1/(count+eps)

// ---------------- PTX helpers ----------------
__device__ __forceinline__ uint32_t smem_u32(const void* p) {
    uint32_t a;
    asm("{ .reg .u64 t; cvta.to.shared.u64 t, %1; cvt.u32.u64 %0, t; }" : "=r"(a) : "l"(p));
    return a;
}
__device__ __forceinline__ void cp16(uint32_t dst, const void* src) {
    asm volatile("cp.async.cg.shared.global [%0], [%1], 16;" :: "r"(dst), "l"(src));
}
__device__ __forceinline__ void cp_commit() {
    asm volatile("cp.async.commit_group;" ::: "memory");
}
__device__ __forceinline__ void ldm_x4(uint32_t* r, uint32_t addr) {
    asm volatile("ldmatrix.sync.aligned.m8n8.x4.shared.b16 {%0,%1,%2,%3}, [%4];"
                 : "=r"(r[0]), "=r"(r[1]), "=r"(r[2]), "=r"(r[3]) : "r"(addr));
}
__device__ __forceinline__ void ldm_x4_t(uint32_t* r, uint32_t addr) {
    asm volatile("ldmatrix.sync.aligned.m8n8.x4.trans.shared.b16 {%0,%1,%2,%3}, [%4];"
                 : "=r"(r[0]), "=r"(r[1]), "=r"(r[2]), "=r"(r[3]) : "r"(addr));
}
__device__ __forceinline__ void mma_f16(float* d, const uint32_t* a, const uint32_t* b) {
    asm volatile(
        "mma.sync.aligned.m16n8k16.row.col.f32.f16.f16.f32 "
        "{%0,%1,%2,%3}, {%4,%5,%6,%7}, {%8,%9}, {%0,%1,%2,%3};"
        : "+f"(d[0]), "+f"(d[1]), "+f"(d[2]), "+f"(d[3])
        : "r"(a[0]), "r"(a[1]), "r"(a[2]), "r"(a[3]), "r"(b[0]), "r"(b[1]));
}

// smem: stage = A tile (128x128B) + B tile (128x128B) = 32KB, 3 stages
#define A_TILE_BYTES 16384
#define STAGE_BYTES  32768
#define NSTAGE       3
#define SMEM_TOTAL   (NSTAGE * STAGE_BYTES)   // 98304 (x2 CTA = 192KB/SM)
#define HROW         136
// MODE 1 overlay: Yh fp16 [128][136] (34816 B) then Ah fp16 [16][136]
#define YH_ROW       136
#define AH_OFF       34816

// ---------------------------------------------------------------------------
// fp16 tensor-core GEMM, CTA 128n x 128m, 4 warps of 64x64, 2 CTA/SM,
// rotated 3-stage cp.async pipeline (1 barrier / K-chunk).
//   MODE 0: write fp16 (stride M) via smem-staged coalesced stores.
//   MODE 1: fused masked-pooling via tensor-core mma; partials scaled by
//           1/(cnt+eps) and atomicAdd'ed directly into out (Pf).
// ---------------------------------------------------------------------------
template <int K, int MODE>
__global__ void __launch_bounds__(128, 2)
gemm_f16(const __half* __restrict__ X, const __half* __restrict__ W,
         const float* __restrict__ bias,
         __half* __restrict__ Oh, float* __restrict__ Pf, int M)
{
    extern __shared__ char smem[];
    const uint32_t sb = smem_u32(smem);
    const int tid = threadIdx.x, wid = tid >> 5, lane = tid & 31;
    const int nw = wid & 1;
    const int mw = wid >> 1;
    const int b = blockIdx.z;
    const int n0 = blockIdx.x * 128;
    const int mtile = blockIdx.y * 128;
    constexpr int NCH = K >> 6;

    const int slot = tid & 7;
    const int rbase = tid >> 3;
    const uint32_t swz = (uint32_t)((rbase & 7) * 16) ^ (uint32_t)(slot * 16);
    const __half* pa = X + ((size_t)b * NPIX + n0 + rbase) * K + slot * 8;
    const __half* pb = W + (size_t)(mtile + rbase) * K + slot * 8;

    auto load_chunk = [&](int c, int s) {
        const uint32_t st = sb + (uint32_t)s * STAGE_BYTES;
        const __half* sa = pa + (size_t)c * 64;
        const __half* sbp = pb + (size_t)c * 64;
#pragma unroll
        for (int j = 0; j < 8; j++)
            cp16(st + (uint32_t)(rbase + 16 * j) * 128 + swz, sa + (size_t)j * 16 * K);
#pragma unroll
        for (int j = 0; j < 8; j++)
            cp16(st + A_TILE_BYTES + (uint32_t)(rbase + 16 * j) * 128 + swz,
                 sbp + (size_t)j * 16 * K);
        cp_commit();
    };

    float acc[4][8][4];
#pragma unroll
    for (int i = 0; i < 4; i++)
#pragma unroll
        for (int j = 0; j < 8; j++)
#pragma unroll
            for (int q = 0; q < 4; q++) acc[i][j][q] = 0.f;

    const int l7 = lane & 7;
    const int mi = lane >> 3;
    const uint32_t lsw = (uint32_t)(l7 * 16);
    const int a_row_base = nw * 64 + (mi & 1) * 8 + l7;
    const int a_colq = (mi >> 1);
    const int b_row_base = mw * 64 + (mi >> 1) * 8 + l7;
    const int b_colq = (mi & 1);

    uint32_t af[2][4][4], bf[2][4][4];

    auto load_frags = [&](uint32_t abase, uint32_t bbase, int s, int buf) {
#pragma unroll
        for (int nt = 0; nt < 4; nt++)
            ldm_x4(af[buf][nt], abase + (uint32_t)(a_row_base + nt * 16) * 128
                                 + (((uint32_t)(s * 2 + a_colq) * 16) ^ lsw));
#pragma unroll
        for (int u = 0; u < 4; u++)
            ldm_x4(bf[buf][u], bbase + (uint32_t)(b_row_base + u * 16) * 128
                                 + (((uint32_t)(s * 2 + b_colq) * 16) ^ lsw));
    };

    auto mma_group = [&](int buf) {
#pragma unroll
        for (int nt = 0; nt < 4; nt++)
#pragma unroll
            for (int u = 0; u < 4; u++) {
                mma_f16(acc[nt][u * 2 + 0], af[buf][nt], bf[buf][u] + 0);
                mma_f16(acc[nt][u * 2 + 1], af[buf][nt], bf[buf][u] + 2);
            }
    };

    load_chunk(0, 0);
    load_chunk(1, 1);
    asm volatile("cp.async.wait_group 1;" ::: "memory");
    __syncthreads();
    load_frags(sb, sb + A_TILE_BYTES, 0, 0);

#pragma unroll
    for (int c = 0; c < NCH; c++) {
        if (c + 2 < NCH) load_chunk(c + 2, (c + 2) % NSTAGE);
        else             cp_commit();

        const uint32_t abase = sb + (uint32_t)(c % NSTAGE) * STAGE_BYTES;
        const uint32_t bbase = abase + A_TILE_BYTES;

#pragma unroll
        for (int s = 0; s < 3; s++) {
            load_frags(abase, bbase, s + 1, (s + 1) & 1);
            mma_group(s & 1);
        }
        if (c + 1 < NCH) {
            asm volatile("cp.async.wait_group 1;" ::: "memory");
            __syncthreads();
            const uint32_t na = sb + (uint32_t)((c + 1) % NSTAGE) * STAGE_BYTES;
            load_frags(na, na + A_TILE_BYTES, 0, 0);
        }
        mma_group(1);
    }

    // -------- epilogue --------
    const int g = lane >> 2, tg = lane & 3;

    if (MODE == 0) {
        __half* Hsm = (__half*)smem;
        __syncthreads();
#pragma unroll
        for (int nt = 0; nt < 4; nt++) {
            const int nloc = nw * 64 + nt * 16 + g;
#pragma unroll
            for (int u = 0; u < 4; u++)
#pragma unroll
                for (int h = 0; h < 2; h++) {
                    const int m = mw * 64 + u * 16 + h * 8 + tg * 2;
                    const float* cc = acc[nt][u * 2 + h];
                    const float b0 = bias[mtile + m], b1 = bias[mtile + m + 1];
                    __half2 p0, p1;
                    p0.x = __float2half_rn(fmaxf(cc[0] + b0, 0.f));
                    p0.y = __float2half_rn(fmaxf(cc[1] + b1, 0.f));
                    p1.x = __float2half_rn(fmaxf(cc[2] + b0, 0.f));
                    p1.y = __float2half_rn(fmaxf(cc[3] + b1, 0.f));
                    *(__half2*)(Hsm + (size_t)nloc * HROW + m) = p0;
                    *(__half2*)(Hsm + (size_t)(nloc + 8) * HROW + m) = p1;
                }
        }
        __syncthreads();
        const size_t obase = ((size_t)b * NPIX + n0) * (size_t)M + mtile;
        const int ch = (tid & 15) * 8;
        const int r0 = tid >> 4;
#pragma unroll
        for (int i = 0; i < 16; i++) {
            const int row = r0 + i * 8;
            *(uint4*)(Oh + obase + (size_t)row * M + ch) =
                *(const uint4*)(Hsm + (size_t)row * HROW + ch);
        }
    } else {
        // fused pooling via mma: P[16cls x 128ch] = Ah[16 x 128pix] * Yh[128pix x 128ch]
        __half* Yh = (__half*)smem;                    // [128 pix][136]
        __half* Ah = (__half*)(smem + AH_OFF);         // [16 cls][136]
        __syncthreads();
#pragma unroll
        for (int nt = 0; nt < 4; nt++) {
            const int nloc = nw * 64 + nt * 16 + g;
#pragma unroll
            for (int u = 0; u < 4; u++)
#pragma unroll
                for (int h = 0; h < 2; h++) {
                    const int m = mw * 64 + u * 16 + h * 8 + tg * 2;
                    const float* cc = acc[nt][u * 2 + h];
                    const float b0 = bias[m], b1 = bias[m + 1];
                    __half2 p0, p1;
                    p0.x = __float2half_rn(fmaxf(cc[0] + b0, 0.f));
                    p0.y = __float2half_rn(fmaxf(cc[1] + b1, 0.f));
                    p1.x = __float2half_rn(fmaxf(cc[2] + b0, 0.f));
                    p1.y = __float2half_rn(fmaxf(cc[3] + b1, 0.f));
                    *(__half2*)(Yh + (size_t)nloc * YH_ROW + m) = p0;
                    *(__half2*)(Yh + (size_t)(nloc + 8) * YH_ROW + m) = p1;
                }
        }
#pragma unroll
        for (int k = 0; k < 16; k++)
            Ah[k * YH_ROW + tid] = (k < NCLS)
                ? __float2half_rn(g_A[(size_t)(b * NCLS + k) * NPIX + n0 + tid])
                : __half(0.f);
        __syncthreads();

        const uint32_t yh = sb;
        const uint32_t ah = sb + AH_OFF;
        const int c0 = wid * 32;
        float pc[4][4];
#pragma unroll
        for (int t = 0; t < 4; t++)
#pragma unroll
            for (int q = 0; q < 4; q++) pc[t][q] = 0.f;

#pragma unroll
        for (int ks = 0; ks < 8; ks++) {
            uint32_t Af[4];
            ldm_x4(Af, ah + (uint32_t)((mi & 1) * 8 + l7) * (YH_ROW * 2)
                       + (uint32_t)(ks * 32 + (mi >> 1) * 16));
#pragma unroll
            for (int cg = 0; cg < 2; cg++) {
                uint32_t Bf[4];
                ldm_x4_t(Bf, yh + (uint32_t)(ks * 16 + (mi & 1) * 8 + l7) * (YH_ROW * 2)
                             + (uint32_t)(c0 + cg * 16 + (mi >> 1) * 8) * 2);
                mma_f16(pc[cg * 2 + 0], Af, Bf + 0);
                mma_f16(pc[cg * 2 + 1], Af, Bf + 2);
            }
        }
        // class g (0..7); scale by 1/(cnt+eps) and atomically accumulate into out
        const float inv = g_cnt[b * NCLS + g];
        float* dst = Pf + ((size_t)b * NCLS + g) * 128;
#pragma unroll
        for (int t = 0; t < 4; t++) {
            atomicAdd(dst + c0 + t * 8 + tg * 2 + 0, pc[t][0] * inv);
            atomicAdd(dst + c0 + t * 8 + tg * 2 + 1, pc[t][1] * inv);
        }
    }
}

// ---------------------------------------------------------------------------
// prep_all: one kernel, role dispatch by block range. 256 threads/block.
//   [0,512)     : weight fp16 conversion
//   [512,6912)  : feature transpose (R13 float-smem version, half2 stores)
//   [6912,7312) : bilinear label-mass gather
//   [7312,7328) : per-batch histogram -> inv count, presence, zero out region
// ---------------------------------------------------------------------------
#define PB_W    512
#define PB_T    6912
#define PB_G    7312
#define PB_H    7328

__global__ void __launch_bounds__(256)
prep_all(const float* __restrict__ w1, const float* __restrict__ w2,
         const float* __restrict__ w3, const float* __restrict__ f,
         const int* __restrict__ lbl, float* __restrict__ out)
{
    __shared__ float ts[64][65];
    const int bx = blockIdx.x, tid = threadIdx.x;

    if (bx < PB_W) {
        const int i = bx * 256 + tid;
        if (i < 512 * 256) g_w1[i] = __float2half_rn(w1[i]);
        if (i < 256 * 512) g_w2[i] = __float2half_rn(w2[i]);
        if (i < 128 * 256) g_w3[i] = __float2half_rn(w3[i]);
        return;
    }
    if (bx < PB_T) {
        // transpose tile: 64 channels x 64 pixels (R13 proven version)
        const int t = bx - PB_W;
        const int nt = t % 100;
        const int rem = t / 100;
        const int ct = rem & 3;
        const int b = rem >> 2;
        const int n0 = nt * 64, c0 = ct * 64;
        const int q = tid & 15, r = tid >> 4;
#pragma unroll
        for (int cc = 0; cc < 64; cc += 16) {
            float4 v = *(const float4*)(f + ((size_t)b * 256 + c0 + cc + r) * NPIX
                                          + n0 + q * 4);
            ts[cc + r][q * 4 + 0] = v.x;
            ts[cc + r][q * 4 + 1] = v.y;
            ts[cc + r][q * 4 + 2] = v.z;
            ts[cc + r][q * 4 + 3] = v.w;
        }
        __syncthreads();
        const int j = tid & 31;
        const int rr = tid >> 5;
#pragma unroll
        for (int p = 0; p < 8; p++) {
            const int nn = rr + p * 8;
            __half2 h;
            h.x = __float2half_rn(ts[2 * j][nn]);
            h.y = __float2half_rn(ts[2 * j + 1][nn]);
            *(__half2*)(g_XA + ((size_t)b * NPIX + n0 + nn) * 256 + c0 + 2 * j) = h;
        }
        return;
    }
    if (bx < PB_G) {
        const int idx = (bx - PB_T) * 256 + tid;
        const int jx = idx % INP;
        const int t = idx / INP;
        const int jy = t % INP;
        const int b = t / INP;
        const int* L = lbl + (size_t)b * OUTP * OUTP;

        int yo[4], xo[4];
        float wy[4], wx[4];
        yo[0] = 2 * jy;     wy[0] = (jy == 0) ? 1.0f : 0.75f;
        yo[1] = 2 * jy + 1; wy[1] = (jy == INP - 1) ? 1.0f : 0.75f;
        yo[2] = (jy > 0) ? 2 * jy - 1 : 0;         wy[2] = (jy > 0) ? 0.25f : 0.f;
        yo[3] = (jy < INP - 1) ? 2 * jy + 2 : 0;   wy[3] = (jy < INP - 1) ? 0.25f : 0.f;
        xo[0] = 2 * jx;     wx[0] = (jx == 0) ? 1.0f : 0.75f;
        xo[1] = 2 * jx + 1; wx[1] = (jx == INP - 1) ? 1.0f : 0.75f;
        xo[2] = (jx > 0) ? 2 * jx - 1 : 0;         wx[2] = (jx > 0) ? 0.25f : 0.f;
        xo[3] = (jx < INP - 1) ? 2 * jx + 2 : 0;   wx[3] = (jx < INP - 1) ? 0.25f : 0.f;

        float a[NCLS] = {0.f, 0.f, 0.f, 0.f, 0.f, 0.f, 0.f, 0.f};
#pragma unroll
        for (int iy = 0; iy < 4; iy++) {
            if (wy[iy] == 0.f) continue;
            const int* Lr = L + yo[iy] * OUTP;
#pragma unroll
            for (int ix = 0; ix < 4; ix++) {
                const float w = wy[iy] * wx[ix];
                if (w != 0.f) a[Lr[xo[ix]]] += w;
            }
        }
        const int cell = jy * INP + jx;
#pragma unroll
        for (int k = 0; k < NCLS; k++)
            g_A[(size_t)(b * NCLS + k) * NPIX + cell] = a[k];
        return;
    }
    {
        __shared__ int h[NCLS];
        const int b = bx - PB_G;
        if (tid < NCLS) h[tid] = 0;
        __syncthreads();
        const int* L = lbl + (size_t)b * OUTP * OUTP;
        for (int i = tid; i < OUTP * OUTP; i += 256)
            atomicAdd(&h[L[i]], 1);
        __syncthreads();
        if (tid < NCLS) {
            const float cv = (float)h[tid];
            g_cnt[b * NCLS + tid] = 1.f / (cv + 1e-8f);
            out[16384 + b * NCLS + tid] = (cv > 0.f) ? 1.f : 0.f;
        }
        // zero this batch's pooled region (out is poisoned each timing run)
        for (int i = tid; i < NCLS * 128; i += 256)
            out[(size_t)b * NCLS * 128 + i] = 0.f;
    }
}

// ---------------------------------------------------------------------------
extern "C" void kernel_launch(void* const* d_in, const int* in_sizes, int n_in,
                              void* d_out, int out_size) {
    const float* feature = (const float*)d_in[0];
    const int*   label   = (const int*)d_in[1];
    const float* w1 = (const float*)d_in[2];
    const float* b1 = (const float*)d_in[3];
    const float* w2 = (const float*)d_in[4];
    const float* b2 = (const float*)d_in[5];
    const float* w3 = (const float*)d_in[6];
    const float* b3 = (const float*)d_in[7];
    float* out = (float*)d_out;

    void *xa, *xb, *w1d, *w2d, *w3d;
    cudaGetSymbolAddress(&xa, g_XA);
    cudaGetSymbolAddress(&xb, g_XB);
    cudaGetSymbolAddress(&w1d, g_w1);
    cudaGetSymbolAddress(&w2d, g_w2);
    cudaGetSymbolAddress(&w3d, g_w3);

    cudaFuncSetAttribute(gemm_f16<256, 0>, cudaFuncAttributeMaxDynamicSharedMemorySize, SMEM_TOTAL);
    cudaFuncSetAttribute(gemm_f16<512, 0>, cudaFuncAttributeMaxDynamicSharedMemorySize, SMEM_TOTAL);
    cudaFuncSetAttribute(gemm_f16<256, 1>, cudaFuncAttributeMaxDynamicSharedMemorySize, SMEM_TOTAL);

    prep_all<<<PB_H, 256>>>(w1, w2, w3, feature, label, out);

    // Y1 = relu(W1 Ft + b1): [b][n][512] fp16
    gemm_f16<256, 0><<<dim3(50, 4, 16), 128, SMEM_TOTAL>>>(
        (const __half*)xa, (const __half*)w1d, b1, (__half*)xb, nullptr, 512);
    // Y2 = relu(W2 Y1 + b2): [b][n][256] fp16
    gemm_f16<512, 0><<<dim3(50, 2, 16), 128, SMEM_TOTAL>>>(
        (const __half*)xb, (const __half*)w2d, b2, (__half*)xa, nullptr, 256);
    // Y3 GEMM + mma pooling + scaled atomic accumulation into out
    gemm_f16<256, 1><<<dim3(50, 1, 16), 128, SMEM_TOTAL>>>(
        (const __half*)xa, (const __half*)w3d, b3, nullptr, out, 128);
}